// round 1
// baseline (speedup 1.0000x reference)
#include <cuda_runtime.h>
#include <math.h>

#define BB    2
#define SS    2048
#define DIMV  2048
#define H     16
#define DK    128
#define DV    128
#define KD    2048
#define VD    2048
#define KCONV 4
#define BS    (BB*SS)   // 4096

// ---------------- scratch (static __device__, no allocs) ----------------
__device__ float g_qlin[BS*KD];
__device__ float g_klin[BS*KD];
__device__ float g_vlin[BS*VD];
__device__ float g_glin[BS*VD];
__device__ float g_qn[BS*KD];
__device__ float g_kn[BS*KD];
__device__ float g_vc[BS*VD];
__device__ float g_o[BS*VD];
__device__ float g_og[BS*VD];
__device__ float g_g[BS*H];
__device__ float g_beta[BS*H];

// ---------------- SGEMM NT: C[m,n] = sum_d A[m,d]*B[n,d] ----------------
// A: [M,K] row-major, B: [N,K] row-major, C: [M,N] row-major.
// 128x128 tile, BK=16, 256 threads, 8x8 microtile. M,N,K multiples of 128/16.
#define BM 128
#define BN 128
#define BK 16
__global__ __launch_bounds__(256) void sgemm_nt(
    const float* __restrict__ A, const float* __restrict__ B,
    float* __restrict__ C, int M, int N, int K)
{
    __shared__ __align__(16) float As[BK][132];
    __shared__ __align__(16) float Bs[BK][132];
    int tid = threadIdx.x;
    int mBase = blockIdx.y * BM;
    int nBase = blockIdx.x * BN;
    int tr = tid >> 4;        // 0..15
    int tc = tid & 15;        // 0..15
    float acc[8][8];
    #pragma unroll
    for (int i = 0; i < 8; i++)
        #pragma unroll
        for (int j = 0; j < 8; j++) acc[i][j] = 0.f;

    for (int kb = 0; kb < K; kb += BK) {
        #pragma unroll
        for (int it = 0; it < 2; it++) {
            int f  = tid + it*256;
            int r  = f >> 2;             // 0..127
            int kq = (f & 3) << 2;       // 0,4,8,12
            float4 av = *(const float4*)&A[(size_t)(mBase + r)*K + kb + kq];
            As[kq+0][r] = av.x; As[kq+1][r] = av.y;
            As[kq+2][r] = av.z; As[kq+3][r] = av.w;
            float4 bv = *(const float4*)&B[(size_t)(nBase + r)*K + kb + kq];
            Bs[kq+0][r] = bv.x; Bs[kq+1][r] = bv.y;
            Bs[kq+2][r] = bv.z; Bs[kq+3][r] = bv.w;
        }
        __syncthreads();
        #pragma unroll
        for (int kk = 0; kk < BK; kk++) {
            float a[8], b[8];
            float4 a0 = *(const float4*)&As[kk][tr*8];
            float4 a1 = *(const float4*)&As[kk][tr*8+4];
            float4 b0 = *(const float4*)&Bs[kk][tc*8];
            float4 b1 = *(const float4*)&Bs[kk][tc*8+4];
            a[0]=a0.x;a[1]=a0.y;a[2]=a0.z;a[3]=a0.w;a[4]=a1.x;a[5]=a1.y;a[6]=a1.z;a[7]=a1.w;
            b[0]=b0.x;b[1]=b0.y;b[2]=b0.z;b[3]=b0.w;b[4]=b1.x;b[5]=b1.y;b[6]=b1.z;b[7]=b1.w;
            #pragma unroll
            for (int i = 0; i < 8; i++)
                #pragma unroll
                for (int j = 0; j < 8; j++)
                    acc[i][j] = fmaf(a[i], b[j], acc[i][j]);
        }
        __syncthreads();
    }
    #pragma unroll
    for (int i = 0; i < 8; i++) {
        float* crow = &C[(size_t)(mBase + tr*8 + i)*N + nBase + tc*8];
        float4 v0 = make_float4(acc[i][0], acc[i][1], acc[i][2], acc[i][3]);
        float4 v1 = make_float4(acc[i][4], acc[i][5], acc[i][6], acc[i][7]);
        *(float4*)(crow)     = v0;
        *(float4*)(crow + 4) = v1;
    }
}

// ---------------- a/b projections -> g (decay) and beta ----------------
// block = 128 threads = 4 rows x 32 lanes; lane<16 -> Wa->g, lane>=16 -> Wb->beta
__global__ void ab_kernel(const float* __restrict__ x, const float* __restrict__ Wa,
                          const float* __restrict__ Wb, const float* __restrict__ A_log,
                          const float* __restrict__ dt_bias)
{
    int tid  = threadIdx.x;
    int ty   = tid >> 5;
    int lane = tid & 31;
    int row  = blockIdx.x * 4 + ty;
    const float* w = (lane < H) ? (Wa + (size_t)lane*DIMV) : (Wb + (size_t)(lane - H)*DIMV);
    const float4* x4 = (const float4*)(x + (size_t)row*DIMV);
    const float4* w4 = (const float4*)w;
    float acc = 0.f;
    for (int i = 0; i < DIMV/4; i++) {
        float4 xv = x4[i], wv = w4[i];
        acc += xv.x*wv.x + xv.y*wv.y + xv.z*wv.z + xv.w*wv.w;
    }
    if (lane < H) {
        float z  = acc + dt_bias[lane];
        float sp = (z > 20.f) ? z : log1pf(expf(z));
        g_g[row*H + lane] = expf(-expf(A_log[lane]) * sp);
    } else {
        int h = lane - H;
        g_beta[row*H + h] = 1.f / (1.f + expf(-acc));
    }
}

// ---------------- causal depthwise conv(K=4) + SiLU (+ per-head L2 norm) ----
// grid = (BS, H), block = 128 threads (one per channel within head)
template<bool NORM>
__global__ void conv_kernel(const float* __restrict__ in, float* __restrict__ out,
                            const float* __restrict__ cw, const float* __restrict__ cb)
{
    int bs  = blockIdx.x;
    int h   = blockIdx.y;
    int tid = threadIdx.x;
    int c   = h*128 + tid;
    int s   = bs & (SS - 1);
    const float* wr = cw + (size_t)c*KCONV;
    float acc = cb[c];
    #pragma unroll
    for (int j = 0; j < KCONV; j++) {
        int sp = s - (KCONV-1) + j;
        if (sp >= 0)
            acc = fmaf(in[(size_t)(bs - (KCONV-1) + j)*2048 + c], wr[j], acc);
    }
    acc = acc / (1.f + expf(-acc));   // SiLU
    if (NORM) {
        float ss = acc*acc;
        #pragma unroll
        for (int o = 16; o; o >>= 1) ss += __shfl_xor_sync(0xffffffffu, ss, o);
        __shared__ float sred[4];
        if ((tid & 31) == 0) sred[tid >> 5] = ss;
        __syncthreads();
        float tot = sred[0] + sred[1] + sred[2] + sred[3];
        acc = acc / fmaxf(sqrtf(tot), 1e-12f);
    }
    out[(size_t)bs*2048 + c] = acc;
}

// ---------------- gated delta-rule recurrence ----------------
// State S[128(k),128(v)] per (b,h). DV columns are independent -> split into
// 4 column-groups of 32 across blocks: grid = B*H*4 = 128 blocks, 128 thr.
// thread (kseg=tid/32, col=tid%32) owns S[kseg*32 .. +32)[col] in registers.
__global__ __launch_bounds__(128) void rec_kernel()
{
    int bid    = blockIdx.x;
    int cg     = bid & 3;
    int bh     = bid >> 2;
    int h      = bh & (H - 1);
    int b      = bh >> 4;
    int tid    = threadIdx.x;
    int kseg   = tid >> 5;
    int colIdx = tid & 31;

    const float* kp = g_kn   + (size_t)b*SS*KD + h*DK;
    const float* qp = g_qn   + (size_t)b*SS*KD + h*DK;
    const float* vp = g_vc   + (size_t)b*SS*VD + h*DV + cg*32;
    const float* gp = g_g    + (size_t)b*SS*H  + h;
    const float* bp = g_beta + (size_t)b*SS*H  + h;
    float*       op = g_o    + (size_t)b*SS*VD + h*DV + cg*32;

    __shared__ __align__(16) float ksm[2][128];
    __shared__ __align__(16) float qsm[2][128];
    __shared__ float vsm[2][32];
    __shared__ float gsm[2], bsm[2];
    __shared__ float redr[128], redo[128];

    float St[32];
    #pragma unroll
    for (int i = 0; i < 32; i++) St[i] = 0.f;

    // prologue: load t=0 into buffer 0
    ksm[0][tid] = kp[tid];
    qsm[0][tid] = qp[tid];
    if (tid < 32) vsm[0][tid] = vp[tid];
    if (tid == 0) { gsm[0] = gp[0]; bsm[0] = bp[0]; }
    __syncthreads();

    for (int t = 0; t < SS; t++) {
        int cur = t & 1, nxt = cur ^ 1;
        // prefetch t+1 into registers (hide L2 latency behind compute)
        float knr = 0.f, qnr = 0.f, vnr = 0.f, gnr = 0.f, bnr = 0.f;
        if (t + 1 < SS) {
            knr = kp[(size_t)(t+1)*KD + tid];
            qnr = qp[(size_t)(t+1)*KD + tid];
            if (tid < 32) vnr = vp[(size_t)(t+1)*VD + tid];
            if (tid == 0) { gnr = gp[(size_t)(t+1)*H]; bnr = bp[(size_t)(t+1)*H]; }
        }
        float gv   = gsm[cur];
        float bv   = bsm[cur];
        float vval = vsm[cur][colIdx];
        const float* kc = &ksm[cur][kseg*32];
        const float* qc = &qsm[cur][kseg*32];

        // retrieved[col] partial over this kseg
        float r = 0.f;
        #pragma unroll
        for (int i = 0; i < 32; i += 4) {
            float4 k4 = *(const float4*)(kc + i);
            r = fmaf(St[i],   k4.x, r);
            r = fmaf(St[i+1], k4.y, r);
            r = fmaf(St[i+2], k4.z, r);
            r = fmaf(St[i+3], k4.w, r);
        }
        redr[tid] = r;
        __syncthreads();
        float rs  = redr[colIdx] + redr[colIdx+32] + redr[colIdx+64] + redr[colIdx+96];
        float err = vval - gv*rs;
        float w   = bv*err;

        // fused: S = g*S + k*w ; o_partial += S*q
        float o = 0.f;
        #pragma unroll
        for (int i = 0; i < 32; i += 4) {
            float4 k4 = *(const float4*)(kc + i);
            float4 q4 = *(const float4*)(qc + i);
            St[i]   = fmaf(gv, St[i],   k4.x*w); o = fmaf(St[i],   q4.x, o);
            St[i+1] = fmaf(gv, St[i+1], k4.y*w); o = fmaf(St[i+1], q4.y, o);
            St[i+2] = fmaf(gv, St[i+2], k4.z*w); o = fmaf(St[i+2], q4.z, o);
            St[i+3] = fmaf(gv, St[i+3], k4.w*w); o = fmaf(St[i+3], q4.w, o);
        }
        redo[tid] = o;

        // commit prefetch into the other buffer
        if (t + 1 < SS) {
            ksm[nxt][tid] = knr;
            qsm[nxt][tid] = qnr;
            if (tid < 32) vsm[nxt][tid] = vnr;
            if (tid == 0) { gsm[nxt] = gnr; bsm[nxt] = bnr; }
        }
        __syncthreads();
        if (kseg == 0) {
            float os = redo[colIdx] + redo[colIdx+32] + redo[colIdx+64] + redo[colIdx+96];
            op[(size_t)t*VD + colIdx] = os;
        }
    }
}

// ---------------- RMSNorm + gate (silu(x@Wg.T)) ----------------
__global__ void rmsnorm_gate_kernel(const float* __restrict__ norm_w)
{
    int row = blockIdx.x;
    int tid = threadIdx.x;   // 256
    float vals[8];
    float ss = 0.f;
    #pragma unroll
    for (int i = 0; i < 8; i++) {
        float v = g_o[(size_t)row*VD + i*256 + tid];
        vals[i] = v;
        ss += v*v;
    }
    #pragma unroll
    for (int o = 16; o; o >>= 1) ss += __shfl_xor_sync(0xffffffffu, ss, o);
    __shared__ float sred[8];
    if ((tid & 31) == 0) sred[tid >> 5] = ss;
    __syncthreads();
    float tot = 0.f;
    #pragma unroll
    for (int i = 0; i < 8; i++) tot += sred[i];
    float scale = rsqrtf(tot * (1.f/VD) + 1e-6f);
    #pragma unroll
    for (int i = 0; i < 8; i++) {
        int c = i*256 + tid;
        float gl = g_glin[(size_t)row*VD + c];
        g_og[(size_t)row*VD + c] =
            vals[i] * scale * norm_w[c] * (gl / (1.f + expf(-gl)));
    }
}

// ---------------- launch ----------------
extern "C" void kernel_launch(void* const* d_in, const int* in_sizes, int n_in,
                              void* d_out, int out_size)
{
    const float* x       = (const float*)d_in[0];
    const float* Wq      = (const float*)d_in[1];
    const float* Wk      = (const float*)d_in[2];
    const float* Wv      = (const float*)d_in[3];
    const float* Wa      = (const float*)d_in[4];
    const float* Wb      = (const float*)d_in[5];
    const float* Wg      = (const float*)d_in[6];
    const float* Wo      = (const float*)d_in[7];
    const float* cw_q    = (const float*)d_in[8];
    const float* cb_q    = (const float*)d_in[9];
    const float* cw_k    = (const float*)d_in[10];
    const float* cb_k    = (const float*)d_in[11];
    const float* cw_v    = (const float*)d_in[12];
    const float* cb_v    = (const float*)d_in[13];
    const float* A_log   = (const float*)d_in[14];
    const float* dt_bias = (const float*)d_in[15];
    const float* norm_w  = (const float*)d_in[16];

    float *qlin, *klin, *vlin, *glin, *qn, *kn, *vc, *og;
    cudaGetSymbolAddress((void**)&qlin, g_qlin);
    cudaGetSymbolAddress((void**)&klin, g_klin);
    cudaGetSymbolAddress((void**)&vlin, g_vlin);
    cudaGetSymbolAddress((void**)&glin, g_glin);
    cudaGetSymbolAddress((void**)&qn,   g_qn);
    cudaGetSymbolAddress((void**)&kn,   g_kn);
    cudaGetSymbolAddress((void**)&vc,   g_vc);
    cudaGetSymbolAddress((void**)&og,   g_og);

    dim3 ggrid(KD/BN, BS/BM);   // (16, 32)

    sgemm_nt<<<ggrid, 256>>>(x, Wq, qlin, BS, KD, DIMV);
    sgemm_nt<<<ggrid, 256>>>(x, Wk, klin, BS, KD, DIMV);
    sgemm_nt<<<ggrid, 256>>>(x, Wv, vlin, BS, VD, DIMV);
    sgemm_nt<<<ggrid, 256>>>(x, Wg, glin, BS, VD, DIMV);

    ab_kernel<<<BS/4, 128>>>(x, Wa, Wb, A_log, dt_bias);

    dim3 cgrid(BS, H);
    conv_kernel<true ><<<cgrid, 128>>>(qlin, qn, cw_q, cb_q);
    conv_kernel<true ><<<cgrid, 128>>>(klin, kn, cw_k, cb_k);
    conv_kernel<false><<<cgrid, 128>>>(vlin, vc, cw_v, cb_v);

    rec_kernel<<<BB*H*4, 128>>>();

    rmsnorm_gate_kernel<<<BS, 256>>>(norm_w);

    sgemm_nt<<<ggrid, 256>>>(og, Wo, (float*)d_out, BS, DIMV, VD);
}

// round 2
// speedup vs baseline: 1.7445x; 1.7445x over previous
#include <cuda_runtime.h>
#include <math.h>
#include <stdint.h>

#define BB    2
#define SS    2048
#define DIMV  2048
#define H     16
#define DK    128
#define DV    128
#define KD    2048
#define VD    2048
#define KCONV 4
#define BS    (BB*SS)   // 4096

// ---------------- scratch (static __device__, no allocs) ----------------
__device__ float g_qlin[BS*KD];
__device__ float g_klin[BS*KD];
__device__ float g_vlin[BS*VD];
__device__ float g_glin[BS*VD];
__device__ float g_qn[BS*KD];
__device__ float g_kn[BS*KD];
__device__ float g_vc[BS*VD];
__device__ float g_o[BS*VD];
__device__ float g_og[BS*VD];
__device__ float g_g[BS*H];
__device__ float g_beta[BS*H];

// ---------------- TF32 tensor-core GEMM NT ----------------
// C[m,n] = sum_d A[m,d]*B[n,d]. A:[M,K] row-major, B:[N,K] row-major.
// 128x128 tile, BK=16, 256 threads (8 warps, warp tile 64x32), mma.m16n8k8.tf32.

__device__ __forceinline__ uint32_t f2tf32(float x) {
    uint32_t r;
    asm("cvt.rna.tf32.f32 %0, %1;" : "=r"(r) : "f"(x));
    return r;
}

#define MMA_TF32(d, a, b)                                                      \
    asm volatile(                                                              \
        "mma.sync.aligned.m16n8k8.row.col.f32.tf32.tf32.f32 "                  \
        "{%0,%1,%2,%3},{%4,%5,%6,%7},{%8,%9},{%0,%1,%2,%3};"                   \
        : "+f"(d[0]), "+f"(d[1]), "+f"(d[2]), "+f"(d[3])                       \
        : "r"(a[0]), "r"(a[1]), "r"(a[2]), "r"(a[3]), "r"(b[0]), "r"(b[1]))

#define SMSTRIDE 20   // 16 + 4 pad: (20*g + t) mod 32 is a permutation -> conflict-free

__global__ __launch_bounds__(256) void mma_gemm_nt(
    const float* __restrict__ A, const float* __restrict__ B,
    float* __restrict__ C, int M, int N, int K)
{
    __shared__ uint32_t As[128 * SMSTRIDE];
    __shared__ uint32_t Bs[128 * SMSTRIDE];

    int tid   = threadIdx.x;
    int lane  = tid & 31;
    int warp  = tid >> 5;
    int warpM = warp >> 2;   // 0..1 -> 64 rows
    int warpN = warp & 3;    // 0..3 -> 32 cols
    int mBase = blockIdx.y * 128;
    int nBase = blockIdx.x * 128;
    int g = lane >> 2;       // 0..7
    int t = lane & 3;        // 0..3

    float acc[4][4][4];
    #pragma unroll
    for (int i = 0; i < 4; i++)
        #pragma unroll
        for (int j = 0; j < 4; j++)
            #pragma unroll
            for (int r = 0; r < 4; r++) acc[i][j][r] = 0.f;

    // staging registers: 2 float4 each for A and B tiles (128x16 each)
    float4 ra[2], rb[2];
    {
        #pragma unroll
        for (int i = 0; i < 2; i++) {
            int idx = tid + i * 256;
            int row = idx >> 2;
            int kq  = (idx & 3) << 2;
            ra[i] = *(const float4*)&A[(size_t)(mBase + row) * K + kq];
            rb[i] = *(const float4*)&B[(size_t)(nBase + row) * K + kq];
        }
    }

    for (int kb = 0; kb < K; kb += 16) {
        __syncthreads();
        #pragma unroll
        for (int i = 0; i < 2; i++) {
            int idx = tid + i * 256;
            int row = idx >> 2;
            int kq  = (idx & 3) << 2;
            uint32_t* ap = &As[row * SMSTRIDE + kq];
            ap[0] = f2tf32(ra[i].x); ap[1] = f2tf32(ra[i].y);
            ap[2] = f2tf32(ra[i].z); ap[3] = f2tf32(ra[i].w);
            uint32_t* bp = &Bs[row * SMSTRIDE + kq];
            bp[0] = f2tf32(rb[i].x); bp[1] = f2tf32(rb[i].y);
            bp[2] = f2tf32(rb[i].z); bp[3] = f2tf32(rb[i].w);
        }
        __syncthreads();

        if (kb + 16 < K) {
            #pragma unroll
            for (int i = 0; i < 2; i++) {
                int idx = tid + i * 256;
                int row = idx >> 2;
                int kq  = (idx & 3) << 2;
                ra[i] = *(const float4*)&A[(size_t)(mBase + row) * K + kb + 16 + kq];
                rb[i] = *(const float4*)&B[(size_t)(nBase + row) * K + kb + 16 + kq];
            }
        }

        #pragma unroll
        for (int ks = 0; ks < 2; ks++) {
            int k0 = ks * 8;
            uint32_t af[4][4], bf[4][2];
            #pragma unroll
            for (int mt = 0; mt < 4; mt++) {
                int m = warpM * 64 + mt * 16;
                af[mt][0] = As[(m + g    ) * SMSTRIDE + k0 + t];
                af[mt][1] = As[(m + g + 8) * SMSTRIDE + k0 + t];
                af[mt][2] = As[(m + g    ) * SMSTRIDE + k0 + t + 4];
                af[mt][3] = As[(m + g + 8) * SMSTRIDE + k0 + t + 4];
            }
            #pragma unroll
            for (int nt = 0; nt < 4; nt++) {
                int n = warpN * 32 + nt * 8;
                bf[nt][0] = Bs[(n + g) * SMSTRIDE + k0 + t];
                bf[nt][1] = Bs[(n + g) * SMSTRIDE + k0 + t + 4];
            }
            #pragma unroll
            for (int mt = 0; mt < 4; mt++)
                #pragma unroll
                for (int nt = 0; nt < 4; nt++)
                    MMA_TF32(acc[mt][nt], af[mt], bf[nt]);
        }
    }

    // epilogue: c0=(g,2t) c1=(g,2t+1) c2=(g+8,2t) c3=(g+8,2t+1)
    #pragma unroll
    for (int mt = 0; mt < 4; mt++) {
        #pragma unroll
        for (int nt = 0; nt < 4; nt++) {
            int row = mBase + warpM * 64 + mt * 16 + g;
            int col = nBase + warpN * 32 + nt * 8 + 2 * t;
            float2 v0 = make_float2(acc[mt][nt][0], acc[mt][nt][1]);
            float2 v1 = make_float2(acc[mt][nt][2], acc[mt][nt][3]);
            *(float2*)&C[(size_t)row * N + col]       = v0;
            *(float2*)&C[(size_t)(row + 8) * N + col] = v1;
        }
    }
}

// ---------------- a/b projections -> g (decay) and beta ----------------
__global__ void ab_kernel(const float* __restrict__ x, const float* __restrict__ Wa,
                          const float* __restrict__ Wb, const float* __restrict__ A_log,
                          const float* __restrict__ dt_bias)
{
    int tid  = threadIdx.x;
    int ty   = tid >> 5;
    int lane = tid & 31;
    int row  = blockIdx.x * 4 + ty;
    const float* w = (lane < H) ? (Wa + (size_t)lane*DIMV) : (Wb + (size_t)(lane - H)*DIMV);
    const float4* x4 = (const float4*)(x + (size_t)row*DIMV);
    const float4* w4 = (const float4*)w;
    float acc = 0.f;
    for (int i = 0; i < DIMV/4; i++) {
        float4 xv = x4[i], wv = w4[i];
        acc += xv.x*wv.x + xv.y*wv.y + xv.z*wv.z + xv.w*wv.w;
    }
    if (lane < H) {
        float z  = acc + dt_bias[lane];
        float sp = (z > 20.f) ? z : log1pf(expf(z));
        g_g[row*H + lane] = expf(-expf(A_log[lane]) * sp);
    } else {
        int h = lane - H;
        g_beta[row*H + h] = 1.f / (1.f + expf(-acc));
    }
}

// ---------------- causal depthwise conv(K=4) + SiLU (+ per-head L2 norm) ----
template<bool NORM>
__global__ void conv_kernel(const float* __restrict__ in, float* __restrict__ out,
                            const float* __restrict__ cw, const float* __restrict__ cb)
{
    int bs  = blockIdx.x;
    int h   = blockIdx.y;
    int tid = threadIdx.x;
    int c   = h*128 + tid;
    int s   = bs & (SS - 1);
    const float* wr = cw + (size_t)c*KCONV;
    float acc = cb[c];
    #pragma unroll
    for (int j = 0; j < KCONV; j++) {
        int sp = s - (KCONV-1) + j;
        if (sp >= 0)
            acc = fmaf(in[(size_t)(bs - (KCONV-1) + j)*2048 + c], wr[j], acc);
    }
    acc = acc / (1.f + expf(-acc));   // SiLU
    if (NORM) {
        float ss = acc*acc;
        #pragma unroll
        for (int o = 16; o; o >>= 1) ss += __shfl_xor_sync(0xffffffffu, ss, o);
        __shared__ float sred[4];
        if ((tid & 31) == 0) sred[tid >> 5] = ss;
        __syncthreads();
        float tot = sred[0] + sred[1] + sred[2] + sred[3];
        acc = acc / fmaxf(sqrtf(tot), 1e-12f);
    }
    out[(size_t)bs*2048 + c] = acc;
}

// ---------------- gated delta-rule recurrence ----------------
__global__ __launch_bounds__(128) void rec_kernel()
{
    int bid    = blockIdx.x;
    int cg     = bid & 3;
    int bh     = bid >> 2;
    int h      = bh & (H - 1);
    int b      = bh >> 4;
    int tid    = threadIdx.x;
    int kseg   = tid >> 5;
    int colIdx = tid & 31;

    const float* kp = g_kn   + (size_t)b*SS*KD + h*DK;
    const float* qp = g_qn   + (size_t)b*SS*KD + h*DK;
    const float* vp = g_vc   + (size_t)b*SS*VD + h*DV + cg*32;
    const float* gp = g_g    + (size_t)b*SS*H  + h;
    const float* bp = g_beta + (size_t)b*SS*H  + h;
    float*       op = g_o    + (size_t)b*SS*VD + h*DV + cg*32;

    __shared__ __align__(16) float ksm[2][128];
    __shared__ __align__(16) float qsm[2][128];
    __shared__ float vsm[2][32];
    __shared__ float gsm[2], bsm[2];
    __shared__ float redr[128], redo[128];

    float St[32];
    #pragma unroll
    for (int i = 0; i < 32; i++) St[i] = 0.f;

    ksm[0][tid] = kp[tid];
    qsm[0][tid] = qp[tid];
    if (tid < 32) vsm[0][tid] = vp[tid];
    if (tid == 0) { gsm[0] = gp[0]; bsm[0] = bp[0]; }
    __syncthreads();

    for (int t = 0; t < SS; t++) {
        int cur = t & 1, nxt = cur ^ 1;
        float knr = 0.f, qnr = 0.f, vnr = 0.f, gnr = 0.f, bnr = 0.f;
        if (t + 1 < SS) {
            knr = kp[(size_t)(t+1)*KD + tid];
            qnr = qp[(size_t)(t+1)*KD + tid];
            if (tid < 32) vnr = vp[(size_t)(t+1)*VD + tid];
            if (tid == 0) { gnr = gp[(size_t)(t+1)*H]; bnr = bp[(size_t)(t+1)*H]; }
        }
        float gv   = gsm[cur];
        float bv   = bsm[cur];
        float vval = vsm[cur][colIdx];
        const float* kc = &ksm[cur][kseg*32];
        const float* qc = &qsm[cur][kseg*32];

        float r = 0.f;
        #pragma unroll
        for (int i = 0; i < 32; i += 4) {
            float4 k4 = *(const float4*)(kc + i);
            r = fmaf(St[i],   k4.x, r);
            r = fmaf(St[i+1], k4.y, r);
            r = fmaf(St[i+2], k4.z, r);
            r = fmaf(St[i+3], k4.w, r);
        }
        redr[tid] = r;
        __syncthreads();
        float rs  = redr[colIdx] + redr[colIdx+32] + redr[colIdx+64] + redr[colIdx+96];
        float err = vval - gv*rs;
        float w   = bv*err;

        float o = 0.f;
        #pragma unroll
        for (int i = 0; i < 32; i += 4) {
            float4 k4 = *(const float4*)(kc + i);
            float4 q4 = *(const float4*)(qc + i);
            St[i]   = fmaf(gv, St[i],   k4.x*w); o = fmaf(St[i],   q4.x, o);
            St[i+1] = fmaf(gv, St[i+1], k4.y*w); o = fmaf(St[i+1], q4.y, o);
            St[i+2] = fmaf(gv, St[i+2], k4.z*w); o = fmaf(St[i+2], q4.z, o);
            St[i+3] = fmaf(gv, St[i+3], k4.w*w); o = fmaf(St[i+3], q4.w, o);
        }
        redo[tid] = o;

        if (t + 1 < SS) {
            ksm[nxt][tid] = knr;
            qsm[nxt][tid] = qnr;
            if (tid < 32) vsm[nxt][tid] = vnr;
            if (tid == 0) { gsm[nxt] = gnr; bsm[nxt] = bnr; }
        }
        __syncthreads();
        if (kseg == 0) {
            float os = redo[colIdx] + redo[colIdx+32] + redo[colIdx+64] + redo[colIdx+96];
            op[(size_t)t*VD + colIdx] = os;
        }
    }
}

// ---------------- RMSNorm + gate (silu(x@Wg.T)) ----------------
__global__ void rmsnorm_gate_kernel(const float* __restrict__ norm_w)
{
    int row = blockIdx.x;
    int tid = threadIdx.x;   // 256
    float vals[8];
    float ss = 0.f;
    #pragma unroll
    for (int i = 0; i < 8; i++) {
        float v = g_o[(size_t)row*VD + i*256 + tid];
        vals[i] = v;
        ss += v*v;
    }
    #pragma unroll
    for (int o = 16; o; o >>= 1) ss += __shfl_xor_sync(0xffffffffu, ss, o);
    __shared__ float sred[8];
    if ((tid & 31) == 0) sred[tid >> 5] = ss;
    __syncthreads();
    float tot = 0.f;
    #pragma unroll
    for (int i = 0; i < 8; i++) tot += sred[i];
    float scale = rsqrtf(tot * (1.f/VD) + 1e-6f);
    #pragma unroll
    for (int i = 0; i < 8; i++) {
        int c = i*256 + tid;
        float gl = g_glin[(size_t)row*VD + c];
        g_og[(size_t)row*VD + c] =
            vals[i] * scale * norm_w[c] * (gl / (1.f + expf(-gl)));
    }
}

// ---------------- launch ----------------
extern "C" void kernel_launch(void* const* d_in, const int* in_sizes, int n_in,
                              void* d_out, int out_size)
{
    const float* x       = (const float*)d_in[0];
    const float* Wq      = (const float*)d_in[1];
    const float* Wk      = (const float*)d_in[2];
    const float* Wv      = (const float*)d_in[3];
    const float* Wa      = (const float*)d_in[4];
    const float* Wb      = (const float*)d_in[5];
    const float* Wg      = (const float*)d_in[6];
    const float* Wo      = (const float*)d_in[7];
    const float* cw_q    = (const float*)d_in[8];
    const float* cb_q    = (const float*)d_in[9];
    const float* cw_k    = (const float*)d_in[10];
    const float* cb_k    = (const float*)d_in[11];
    const float* cw_v    = (const float*)d_in[12];
    const float* cb_v    = (const float*)d_in[13];
    const float* A_log   = (const float*)d_in[14];
    const float* dt_bias = (const float*)d_in[15];
    const float* norm_w  = (const float*)d_in[16];

    float *qlin, *klin, *vlin, *glin, *qn, *kn, *vc, *og;
    cudaGetSymbolAddress((void**)&qlin, g_qlin);
    cudaGetSymbolAddress((void**)&klin, g_klin);
    cudaGetSymbolAddress((void**)&vlin, g_vlin);
    cudaGetSymbolAddress((void**)&glin, g_glin);
    cudaGetSymbolAddress((void**)&qn,   g_qn);
    cudaGetSymbolAddress((void**)&kn,   g_kn);
    cudaGetSymbolAddress((void**)&vc,   g_vc);
    cudaGetSymbolAddress((void**)&og,   g_og);

    dim3 ggrid(KD/128, BS/128);   // (16, 32)

    mma_gemm_nt<<<ggrid, 256>>>(x, Wq, qlin, BS, KD, DIMV);
    mma_gemm_nt<<<ggrid, 256>>>(x, Wk, klin, BS, KD, DIMV);
    mma_gemm_nt<<<ggrid, 256>>>(x, Wv, vlin, BS, VD, DIMV);
    mma_gemm_nt<<<ggrid, 256>>>(x, Wg, glin, BS, VD, DIMV);

    ab_kernel<<<BS/4, 128>>>(x, Wa, Wb, A_log, dt_bias);

    dim3 cgrid(BS, H);
    conv_kernel<true ><<<cgrid, 128>>>(qlin, qn, cw_q, cb_q);
    conv_kernel<true ><<<cgrid, 128>>>(klin, kn, cw_k, cb_k);
    conv_kernel<false><<<cgrid, 128>>>(vlin, vc, cw_v, cb_v);

    rec_kernel<<<BB*H*4, 128>>>();

    rmsnorm_gate_kernel<<<BS, 256>>>(norm_w);

    mma_gemm_nt<<<ggrid, 256>>>(og, Wo, (float*)d_out, BS, DIMV, VD);
}

// round 3
// speedup vs baseline: 2.2010x; 1.2617x over previous
#include <cuda_runtime.h>
#include <math.h>
#include <stdint.h>

#define BB    2
#define SS    2048
#define DIMV  2048
#define H     16
#define DK    128
#define DV    128
#define KD    2048
#define VD    2048
#define KCONV 4
#define BS    (BB*SS)   // 4096

// ---------------- scratch (static __device__, no allocs) ----------------
__device__ float    g_qlin[BS*KD];
__device__ float    g_klin[BS*KD];
__device__ float    g_vlin[BS*VD];
__device__ float    g_glin[BS*VD];
__device__ float    g_qn[BS*KD];
__device__ float    g_kn[BS*KD];
__device__ float    g_vc[BS*VD];
__device__ float    g_o[BS*VD];
__device__ float    g_g[BS*H];
__device__ float    g_beta[BS*H];
__device__ uint32_t g_xt[BS*DIMV];        // x in tf32 bits
__device__ uint32_t g_w4[4*KD*DIMV];      // Wq|Wk|Wv|Wg in tf32 bits
__device__ uint32_t g_wot[DIMV*VD];       // Wo in tf32 bits
__device__ uint32_t g_ogt[BS*VD];         // rmsnorm*gate output in tf32 bits

__device__ __forceinline__ uint32_t f2tf32(float x) {
    uint32_t r;
    asm("cvt.rna.tf32.f32 %0, %1;" : "=r"(r) : "f"(x));
    return r;
}

// ---------------- fp32 -> tf32 conversion (elementwise) ----------------
__global__ void cvt_tf32_kernel(const float* __restrict__ in, uint32_t* __restrict__ out)
{
    size_t i = ((size_t)blockIdx.x * 256 + threadIdx.x) * 4;
    float4 v = *(const float4*)(in + i);
    uint4 u;
    u.x = f2tf32(v.x); u.y = f2tf32(v.y); u.z = f2tf32(v.z); u.w = f2tf32(v.w);
    *(uint4*)(out + i) = u;
}

// ---------------- TF32 tensor-core GEMM NT, cp.async double-buffered ----
// C[m,n] = sum_d A[m,d]*B[n,d]. A,B already tf32 bits. 128x128 tile, BK=32,
// 256 threads (8 warps, warp tile 64x32), mma.m16n8k8.
#define SMS 36            // word stride: 36 mod 32 = 4 -> LDS bank = lane perm
#define STAGE_WORDS (128*SMS)

#define MMA_TF32(d, a, b)                                                      \
    asm volatile(                                                              \
        "mma.sync.aligned.m16n8k8.row.col.f32.tf32.tf32.f32 "                  \
        "{%0,%1,%2,%3},{%4,%5,%6,%7},{%8,%9},{%0,%1,%2,%3};"                   \
        : "+f"(d[0]), "+f"(d[1]), "+f"(d[2]), "+f"(d[3])                       \
        : "r"(a[0]), "r"(a[1]), "r"(a[2]), "r"(a[3]), "r"(b[0]), "r"(b[1]))

__device__ __forceinline__ void cpa16(uint32_t saddr, const void* gptr) {
    asm volatile("cp.async.ca.shared.global [%0], [%1], 16;\n" :: "r"(saddr), "l"(gptr));
}

struct GemmPtrs {
    const uint32_t* Bw[4];
    float*          C[4];
};

__global__ __launch_bounds__(256, 2) void mma_gemm_tf32(
    const uint32_t* __restrict__ A, GemmPtrs P, int K, int N)
{
    extern __shared__ uint32_t smem[];
    uint32_t* As = smem;                     // [2][STAGE_WORDS]
    uint32_t* Bs = smem + 2*STAGE_WORDS;     // [2][STAGE_WORDS]

    int buf = blockIdx.x >> 4;
    int nb  = blockIdx.x & 15;
    const uint32_t* Bw = P.Bw[buf];
    float*          C  = P.C[buf];

    int tid   = threadIdx.x;
    int lane  = tid & 31;
    int warp  = tid >> 5;
    int warpM = warp >> 2;
    int warpN = warp & 3;
    int mBase = blockIdx.y * 128;
    int nBase = nb * 128;
    int g = lane >> 2;
    int t = lane & 3;

    uint32_t sA = (uint32_t)__cvta_generic_to_shared(As);
    uint32_t sB = (uint32_t)__cvta_generic_to_shared(Bs);

    float acc[4][4][4];
    #pragma unroll
    for (int i = 0; i < 4; i++)
        #pragma unroll
        for (int j = 0; j < 4; j++)
            #pragma unroll
            for (int r = 0; r < 4; r++) acc[i][j][r] = 0.f;

    // stage loader: 128 rows x 32 words, 4 x 16B per thread per matrix
    #define LOAD_STAGE(stg, kb)                                                 \
        do {                                                                    \
            _Pragma("unroll")                                                   \
            for (int j = 0; j < 4; j++) {                                       \
                int idx = tid + j * 256;                                        \
                int row = idx >> 3;                                             \
                int kc  = (idx & 7) << 2;                                       \
                cpa16(sA + ((stg)*STAGE_WORDS + row*SMS + kc)*4,                \
                      &A[(size_t)(mBase + row)*K + (kb) + kc]);                 \
                cpa16(sB + ((stg)*STAGE_WORDS + row*SMS + kc)*4,                \
                      &Bw[(size_t)(nBase + row)*K + (kb) + kc]);                \
            }                                                                   \
            asm volatile("cp.async.commit_group;\n");                           \
        } while (0)

    LOAD_STAGE(0, 0);
    int NIT = K >> 5;
    for (int it = 0; it < NIT; it++) {
        int cur = it & 1;
        if (it + 1 < NIT) {
            LOAD_STAGE(cur ^ 1, (it + 1) << 5);
            asm volatile("cp.async.wait_group 1;\n");
        } else {
            asm volatile("cp.async.wait_group 0;\n");
        }
        __syncthreads();

        const uint32_t* Ac = As + cur*STAGE_WORDS;
        const uint32_t* Bc = Bs + cur*STAGE_WORDS;
        #pragma unroll
        for (int ks = 0; ks < 4; ks++) {
            int k0 = ks * 8;
            uint32_t af[4][4], bf[4][2];
            #pragma unroll
            for (int mt = 0; mt < 4; mt++) {
                int m = warpM*64 + mt*16;
                af[mt][0] = Ac[(m + g    )*SMS + k0 + t];
                af[mt][1] = Ac[(m + g + 8)*SMS + k0 + t];
                af[mt][2] = Ac[(m + g    )*SMS + k0 + t + 4];
                af[mt][3] = Ac[(m + g + 8)*SMS + k0 + t + 4];
            }
            #pragma unroll
            for (int nt = 0; nt < 4; nt++) {
                int n = warpN*32 + nt*8;
                bf[nt][0] = Bc[(n + g)*SMS + k0 + t];
                bf[nt][1] = Bc[(n + g)*SMS + k0 + t + 4];
            }
            #pragma unroll
            for (int mt = 0; mt < 4; mt++)
                #pragma unroll
                for (int nt = 0; nt < 4; nt++)
                    MMA_TF32(acc[mt][nt], af[mt], bf[nt]);
        }
        __syncthreads();
    }

    #pragma unroll
    for (int mt = 0; mt < 4; mt++) {
        #pragma unroll
        for (int nt = 0; nt < 4; nt++) {
            int row = mBase + warpM*64 + mt*16 + g;
            int col = nBase + warpN*32 + nt*8 + 2*t;
            *(float2*)&C[(size_t)row * N + col] =
                make_float2(acc[mt][nt][0], acc[mt][nt][1]);
            *(float2*)&C[(size_t)(row + 8) * N + col] =
                make_float2(acc[mt][nt][2], acc[mt][nt][3]);
        }
    }
}

// ---------------- a/b projections -> g (decay) and beta ----------------
__global__ void ab_kernel(const float* __restrict__ x, const float* __restrict__ Wa,
                          const float* __restrict__ Wb, const float* __restrict__ A_log,
                          const float* __restrict__ dt_bias)
{
    int tid  = threadIdx.x;
    int ty   = tid >> 5;
    int lane = tid & 31;
    int row  = blockIdx.x * 4 + ty;
    const float* w = (lane < H) ? (Wa + (size_t)lane*DIMV) : (Wb + (size_t)(lane - H)*DIMV);
    const float4* x4 = (const float4*)(x + (size_t)row*DIMV);
    const float4* w4 = (const float4*)w;
    float acc = 0.f;
    for (int i = 0; i < DIMV/4; i++) {
        float4 xv = x4[i], wv = w4[i];
        acc += xv.x*wv.x + xv.y*wv.y + xv.z*wv.z + xv.w*wv.w;
    }
    if (lane < H) {
        float z  = acc + dt_bias[lane];
        float sp = (z > 20.f) ? z : log1pf(expf(z));
        g_g[row*H + lane] = expf(-expf(A_log[lane]) * sp);
    } else {
        int h = lane - H;
        g_beta[row*H + h] = 1.f / (1.f + expf(-acc));
    }
}

// ---------------- causal depthwise conv(K=4) + SiLU (+ per-head L2 norm) ----
template<bool NORM>
__global__ void conv_kernel(const float* __restrict__ in, float* __restrict__ out,
                            const float* __restrict__ cw, const float* __restrict__ cb)
{
    int bs  = blockIdx.x;
    int h   = blockIdx.y;
    int tid = threadIdx.x;
    int c   = h*128 + tid;
    int s   = bs & (SS - 1);
    const float* wr = cw + (size_t)c*KCONV;
    float acc = cb[c];
    #pragma unroll
    for (int j = 0; j < KCONV; j++) {
        int sp = s - (KCONV-1) + j;
        if (sp >= 0)
            acc = fmaf(in[(size_t)(bs - (KCONV-1) + j)*2048 + c], wr[j], acc);
    }
    acc = acc / (1.f + expf(-acc));   // SiLU
    if (NORM) {
        float ss = acc*acc;
        #pragma unroll
        for (int o = 16; o; o >>= 1) ss += __shfl_xor_sync(0xffffffffu, ss, o);
        __shared__ float sred[4];
        if ((tid & 31) == 0) sred[tid >> 5] = ss;
        __syncthreads();
        float tot = sred[0] + sred[1] + sred[2] + sred[3];
        acc = acc / fmaxf(sqrtf(tot), 1e-12f);
    }
    out[(size_t)bs*2048 + c] = acc;
}

// ---------------- gated delta-rule recurrence ----------------
__global__ __launch_bounds__(128) void rec_kernel()
{
    int bid    = blockIdx.x;
    int cg     = bid & 3;
    int bh     = bid >> 2;
    int h      = bh & (H - 1);
    int b      = bh >> 4;
    int tid    = threadIdx.x;
    int kseg   = tid >> 5;
    int colIdx = tid & 31;

    const float* kp = g_kn   + (size_t)b*SS*KD + h*DK;
    const float* qp = g_qn   + (size_t)b*SS*KD + h*DK;
    const float* vp = g_vc   + (size_t)b*SS*VD + h*DV + cg*32;
    const float* gp = g_g    + (size_t)b*SS*H  + h;
    const float* bp = g_beta + (size_t)b*SS*H  + h;
    float*       op = g_o    + (size_t)b*SS*VD + h*DV + cg*32;

    __shared__ __align__(16) float ksm[2][128];
    __shared__ __align__(16) float qsm[2][128];
    __shared__ float vsm[2][32];
    __shared__ float gsm[2], bsm[2];
    __shared__ float redr[128], redo[128];

    float St[32];
    #pragma unroll
    for (int i = 0; i < 32; i++) St[i] = 0.f;

    ksm[0][tid] = kp[tid];
    qsm[0][tid] = qp[tid];
    if (tid < 32) vsm[0][tid] = vp[tid];
    if (tid == 0) { gsm[0] = gp[0]; bsm[0] = bp[0]; }
    __syncthreads();

    for (int t = 0; t < SS; t++) {
        int cur = t & 1, nxt = cur ^ 1;
        float knr = 0.f, qnr = 0.f, vnr = 0.f, gnr = 0.f, bnr = 0.f;
        if (t + 1 < SS) {
            knr = kp[(size_t)(t+1)*KD + tid];
            qnr = qp[(size_t)(t+1)*KD + tid];
            if (tid < 32) vnr = vp[(size_t)(t+1)*VD + tid];
            if (tid == 0) { gnr = gp[(size_t)(t+1)*H]; bnr = bp[(size_t)(t+1)*H]; }
        }
        float gv   = gsm[cur];
        float bv   = bsm[cur];
        float vval = vsm[cur][colIdx];
        const float* kc = &ksm[cur][kseg*32];
        const float* qc = &qsm[cur][kseg*32];

        // retrieved partial, 4 independent chains
        float r0=0.f, r1=0.f, r2=0.f, r3=0.f;
        #pragma unroll
        for (int i = 0; i < 32; i += 4) {
            float4 k4 = *(const float4*)(kc + i);
            r0 = fmaf(St[i],   k4.x, r0);
            r1 = fmaf(St[i+1], k4.y, r1);
            r2 = fmaf(St[i+2], k4.z, r2);
            r3 = fmaf(St[i+3], k4.w, r3);
        }
        redr[tid] = (r0 + r1) + (r2 + r3);
        __syncthreads();
        float rs  = redr[colIdx] + redr[colIdx+32] + redr[colIdx+64] + redr[colIdx+96];
        float err = vval - gv*rs;
        float w   = bv*err;

        // S = g*S + k*w ; o += S*q  (4 independent o-chains)
        float o0=0.f, o1=0.f, o2=0.f, o3=0.f;
        #pragma unroll
        for (int i = 0; i < 32; i += 4) {
            float4 k4 = *(const float4*)(kc + i);
            float4 q4 = *(const float4*)(qc + i);
            St[i]   = fmaf(gv, St[i],   k4.x*w); o0 = fmaf(St[i],   q4.x, o0);
            St[i+1] = fmaf(gv, St[i+1], k4.y*w); o1 = fmaf(St[i+1], q4.y, o1);
            St[i+2] = fmaf(gv, St[i+2], k4.z*w); o2 = fmaf(St[i+2], q4.z, o2);
            St[i+3] = fmaf(gv, St[i+3], k4.w*w); o3 = fmaf(St[i+3], q4.w, o3);
        }
        redo[tid] = (o0 + o1) + (o2 + o3);

        if (t + 1 < SS) {
            ksm[nxt][tid] = knr;
            qsm[nxt][tid] = qnr;
            if (tid < 32) vsm[nxt][tid] = vnr;
            if (tid == 0) { gsm[nxt] = gnr; bsm[nxt] = bnr; }
        }
        __syncthreads();
        if (kseg == 0) {
            float os = redo[colIdx] + redo[colIdx+32] + redo[colIdx+64] + redo[colIdx+96];
            op[(size_t)t*VD + colIdx] = os;
        }
    }
}

// ---------------- RMSNorm + gate (silu(x@Wg.T)), emits tf32 bits ---------
__global__ void rmsnorm_gate_kernel(const float* __restrict__ norm_w)
{
    int row = blockIdx.x;
    int tid = threadIdx.x;   // 256
    float vals[8];
    float ss = 0.f;
    #pragma unroll
    for (int i = 0; i < 8; i++) {
        float v = g_o[(size_t)row*VD + i*256 + tid];
        vals[i] = v;
        ss += v*v;
    }
    #pragma unroll
    for (int o = 16; o; o >>= 1) ss += __shfl_xor_sync(0xffffffffu, ss, o);
    __shared__ float sred[8];
    if ((tid & 31) == 0) sred[tid >> 5] = ss;
    __syncthreads();
    float tot = 0.f;
    #pragma unroll
    for (int i = 0; i < 8; i++) tot += sred[i];
    float scale = rsqrtf(tot * (1.f/VD) + 1e-6f);
    #pragma unroll
    for (int i = 0; i < 8; i++) {
        int c = i*256 + tid;
        float gl = g_glin[(size_t)row*VD + c];
        float r  = vals[i] * scale * norm_w[c] * (gl / (1.f + expf(-gl)));
        g_ogt[(size_t)row*VD + c] = f2tf32(r);
    }
}

// ---------------- launch ----------------
extern "C" void kernel_launch(void* const* d_in, const int* in_sizes, int n_in,
                              void* d_out, int out_size)
{
    const float* x       = (const float*)d_in[0];
    const float* Wq      = (const float*)d_in[1];
    const float* Wk      = (const float*)d_in[2];
    const float* Wv      = (const float*)d_in[3];
    const float* Wa      = (const float*)d_in[4];
    const float* Wb      = (const float*)d_in[5];
    const float* Wg      = (const float*)d_in[6];
    const float* Wo      = (const float*)d_in[7];
    const float* cw_q    = (const float*)d_in[8];
    const float* cb_q    = (const float*)d_in[9];
    const float* cw_k    = (const float*)d_in[10];
    const float* cb_k    = (const float*)d_in[11];
    const float* cw_v    = (const float*)d_in[12];
    const float* cb_v    = (const float*)d_in[13];
    const float* A_log   = (const float*)d_in[14];
    const float* dt_bias = (const float*)d_in[15];
    const float* norm_w  = (const float*)d_in[16];

    float *qlin, *klin, *vlin, *glin, *qn, *kn, *vc;
    uint32_t *xt, *w4, *wot, *ogt;
    cudaGetSymbolAddress((void**)&qlin, g_qlin);
    cudaGetSymbolAddress((void**)&klin, g_klin);
    cudaGetSymbolAddress((void**)&vlin, g_vlin);
    cudaGetSymbolAddress((void**)&glin, g_glin);
    cudaGetSymbolAddress((void**)&qn,   g_qn);
    cudaGetSymbolAddress((void**)&kn,   g_kn);
    cudaGetSymbolAddress((void**)&vc,   g_vc);
    cudaGetSymbolAddress((void**)&xt,   g_xt);
    cudaGetSymbolAddress((void**)&w4,   g_w4);
    cudaGetSymbolAddress((void**)&wot,  g_wot);
    cudaGetSymbolAddress((void**)&ogt,  g_ogt);

    static int smem_set = 0;
    if (!smem_set) {
        cudaFuncSetAttribute(mma_gemm_tf32,
                             cudaFuncAttributeMaxDynamicSharedMemorySize,
                             4*STAGE_WORDS*4);
        smem_set = 1;
    }
    size_t gemm_smem = 4*STAGE_WORDS*4;   // 73728 B

    // tf32 conversions
    cvt_tf32_kernel<<<(BS*DIMV)/1024, 256>>>(x,  xt);
    cvt_tf32_kernel<<<(KD*DIMV)/1024, 256>>>(Wq, w4 + 0*(size_t)KD*DIMV);
    cvt_tf32_kernel<<<(KD*DIMV)/1024, 256>>>(Wk, w4 + 1*(size_t)KD*DIMV);
    cvt_tf32_kernel<<<(KD*DIMV)/1024, 256>>>(Wv, w4 + 2*(size_t)KD*DIMV);
    cvt_tf32_kernel<<<(KD*DIMV)/1024, 256>>>(Wg, w4 + 3*(size_t)KD*DIMV);
    cvt_tf32_kernel<<<(DIMV*VD)/1024, 256>>>(Wo, wot);

    // fused q/k/v/g projection GEMM
    GemmPtrs P;
    P.Bw[0] = w4 + 0*(size_t)KD*DIMV; P.C[0] = qlin;
    P.Bw[1] = w4 + 1*(size_t)KD*DIMV; P.C[1] = klin;
    P.Bw[2] = w4 + 2*(size_t)KD*DIMV; P.C[2] = vlin;
    P.Bw[3] = w4 + 3*(size_t)KD*DIMV; P.C[3] = glin;
    mma_gemm_tf32<<<dim3(64, 32), 256, gemm_smem>>>(xt, P, DIMV, KD);

    ab_kernel<<<BS/4, 128>>>(x, Wa, Wb, A_log, dt_bias);

    dim3 cgrid(BS, H);
    conv_kernel<true ><<<cgrid, 128>>>(qlin, qn, cw_q, cb_q);
    conv_kernel<true ><<<cgrid, 128>>>(klin, kn, cw_k, cb_k);
    conv_kernel<false><<<cgrid, 128>>>(vlin, vc, cw_v, cb_v);

    rec_kernel<<<BB*H*4, 128>>>();

    rmsnorm_gate_kernel<<<BS, 256>>>(norm_w);

    // output GEMM
    GemmPtrs Po;
    for (int i = 0; i < 4; i++) { Po.Bw[i] = wot; Po.C[i] = (float*)d_out; }
    mma_gemm_tf32<<<dim3(16, 32), 256, gemm_smem>>>(ogt, Po, VD, DIMV);
}